// round 10
// baseline (speedup 1.0000x reference)
#include <cuda_runtime.h>
#include <cstdint>

#define B 8
#define N 100000
#define V 40
#define NBINS 64000
#define NTILES 63                    // tiles of 1024 bins per batch
#define NTILES_TOT (B * NTILES)      // 504
#define PB_F4 1296000                // float4s per batch in nbr table

// Output layout (float32 elements)
#define O_IDX  0
#define O_HASH 800000
#define O_NBR  1600000
#define O_MASK 43072000

// ---- scratch ----
__device__ int g_voxel[B * N];       // bin id per point
__device__ int g_rank[B * N];        // rank of point within its bin (atomic order)
__device__ int g_hist[B * NBINS];    // counts -> offsets; re-zeroed in fixup
__device__ int g_cursor[B * NBINS];  // copy of offsets (fixup reads this)
__device__ int g_sorted[B * N];      // sorted point indices
__device__ unsigned g_state[NTILES_TOT]; // lookback state; reset by bin_kernel

#define FLAG_AGG (1u << 30)
#define FLAG_PRE (2u << 30)
#define VAL_MASK ((1u << 30) - 1u)

// ---------------------------------------------------------------------------
// bin: 4 points/thread via float4 loads; atomic returns rank-in-bin.
__global__ void bin_kernel(const float* __restrict__ pts) {
    int gi = blockIdx.x * blockDim.x + threadIdx.x;
    if (gi < NTILES_TOT) g_state[gi] = 0u;   // reset lookback state for scan
    if (gi >= (B * N) / 4) return;
    const float4* p4 = (const float4*)pts;
    float4 f0 = __ldg(&p4[3 * gi]);
    float4 f1 = __ldg(&p4[3 * gi + 1]);
    float4 f2 = __ldg(&p4[3 * gi + 2]);
    int b = gi / (N / 4);
    float px[4] = { f0.x, f0.w, f1.z, f2.y };
    float py[4] = { f0.y, f1.x, f1.w, f2.z };
    float pz[4] = { f0.z, f1.y, f2.x, f2.w };
    int bins[4], rnk[4];
    #pragma unroll
    for (int k = 0; k < 4; k++) {
        int cx = (int)(px[k] * (float)(V - 1));
        int cy = (int)(py[k] * (float)(V - 1));
        int cz = (int)(pz[k] * (float)(V - 1));
        bins[k] = cx * (V * V) + cy * V + cz;
    }
    #pragma unroll
    for (int k = 0; k < 4; k++)
        rnk[k] = atomicAdd(&g_hist[b * NBINS + bins[k]], 1);
    *(int4*)(g_voxel + 4 * gi) = make_int4(bins[0], bins[1], bins[2], bins[3]);
    *(int4*)(g_rank  + 4 * gi) = make_int4(rnk[0],  rnk[1],  rnk[2],  rnk[3]);
}

// ---------------------------------------------------------------------------
// Single-pass decoupled-lookback scan; also writes the mask
// (mask[bin] = count>0 && offset[bin]+count < N).
__global__ void scan_kernel(float* __restrict__ out) {
    int tile = blockIdx.x;               // 0..503
    int b = tile / NTILES;
    int t = tile - b * NTILES;
    int tid = threadIdx.x;
    int tb = t * 1024 + tid * 4;

    int4 v = make_int4(0, 0, 0, 0);
    if (tb < NBINS) v = *(const int4*)(g_hist + b * NBINS + tb);
    int tsum = v.x + v.y + v.z + v.w;

    int lane = tid & 31, warp = tid >> 5;
    int x = tsum;
    #pragma unroll
    for (int o = 1; o < 32; o <<= 1) {
        int tt = __shfl_up_sync(0xFFFFFFFFu, x, o);
        if (lane >= o) x += tt;
    }
    __shared__ int ws[8];
    __shared__ int s_excl;
    if (lane == 31) ws[warp] = x;
    __syncthreads();
    int woff = 0, total = 0;
    #pragma unroll
    for (int w = 0; w < 8; w++) {
        int wv = ws[w];
        woff += (w < warp) ? wv : 0;
        total += wv;
    }

    if (tid == 0) {
        volatile unsigned* st = g_state + b * NTILES;
        if (t == 0) {
            __threadfence();
            st[0] = (unsigned)total | FLAG_PRE;
            s_excl = 0;
        } else {
            __threadfence();
            st[t] = (unsigned)total | FLAG_AGG;
            int excl = 0;
            for (int j = t - 1; j >= 0; ) {
                unsigned s;
                do { s = st[j]; } while (!(s >> 30));
                excl += (int)(s & VAL_MASK);
                if ((s >> 30) == 2u) break;
                j--;
            }
            __threadfence();
            st[t] = (unsigned)(excl + total) | FLAG_PRE;
            s_excl = excl;
        }
    }
    __syncthreads();

    int base = s_excl + woff + x - tsum;
    if (tb < NBINS) {
        int4 o4;
        o4.x = base;
        o4.y = base + v.x;
        o4.z = base + v.x + v.y;
        o4.w = base + v.x + v.y + v.z;
        *(int4*)(g_hist   + b * NBINS + tb) = o4;
        *(int4*)(g_cursor + b * NBINS + tb) = o4;
        float4 m4;
        m4.x = (v.x > 0 && o4.x + v.x < N) ? 1.0f : 0.0f;
        m4.y = (v.y > 0 && o4.y + v.y < N) ? 1.0f : 0.0f;
        m4.z = (v.z > 0 && o4.z + v.z < N) ? 1.0f : 0.0f;
        m4.w = (v.w > 0 && o4.w + v.w < N) ? 1.0f : 0.0f;
        *(float4*)(out + O_MASK + b * NBINS + tb) = m4;
    }
}

// ---------------------------------------------------------------------------
// scatter: NO atomics. pos = offset[bin] + rank. One 4B store into g_sorted.
__global__ void scatter_kernel() {
    int gi = blockIdx.x * blockDim.x + threadIdx.x;
    if (gi >= (B * N) / 4) return;
    int i0 = gi * 4;
    int b = gi / (N / 4);
    int4 vb = *(const int4*)(g_voxel + i0);
    int4 rb = *(const int4*)(g_rank  + i0);
    int bins[4] = { vb.x, vb.y, vb.z, vb.w };
    int rnk[4]  = { rb.x, rb.y, rb.z, rb.w };
    int pos[4];
    #pragma unroll
    for (int k = 0; k < 4; k++)
        pos[k] = g_hist[b * NBINS + bins[k]] + rnk[k];
    int nbase = i0 - b * N;
    #pragma unroll
    for (int k = 0; k < 4; k++)
        g_sorted[b * N + pos[k]] = nbase + k;
}

// ---------------------------------------------------------------------------
// fixup: stability insertion-sort on segments with count>=2 (L2-hot ints);
// re-zeroes g_hist. No output writes.
__global__ void fixup_kernel() {
    int t = blockIdx.x * blockDim.x + threadIdx.x;
    if (t >= B * NBINS) return;
    int b = t / NBINS;
    int bin = t - b * NBINS;
    int s = g_cursor[t];
    int e = (bin == NBINS - 1) ? N : g_cursor[t + 1];
    g_hist[t] = 0;                        // restore count invariant for replay
    if (e - s < 2) return;
    int* seg = g_sorted + b * N;
    for (int a = s + 1; a < e; a++) {
        int key = seg[a];
        int j = a - 1;
        while (j >= s && seg[j] > key) { seg[j + 1] = seg[j]; j--; }
        seg[j + 1] = key;
    }
}

// ---------------------------------------------------------------------------
// write: point-parallel, ILP-4, fully coalesced idx+hash output.
__global__ void write_kernel(float* __restrict__ out) {
    int gi = blockIdx.x * blockDim.x + threadIdx.x;
    if (gi >= (B * N) / 4) return;
    int j0 = gi * 4;
    int b = gi / (N / 4);
    int4 s4 = *(const int4*)(g_sorted + j0);
    int idx[4] = { s4.x, s4.y, s4.z, s4.w };
    float4 fo, fh;
    float* fop = &fo.x;
    float* fhp = &fh.x;
    #pragma unroll
    for (int k = 0; k < 4; k++) {
        int bin = g_voxel[b * N + idx[k]];     // L2-hot random read
        int cx = bin / (V * V);
        int cy = (bin / V) % V;
        int cz = bin % V;
        fop[k] = (float)idx[k];
        fhp[k] = (float)(cx * 10000 + cy * 100 + cz);
    }
    *(float4*)(out + O_IDX  + j0) = fo;
    *(float4*)(out + O_HASH + j0) = fh;
}

// ---------------------------------------------------------------------------
// neighbour table: full-grid pure-store kernel; 2 consecutive float4s per
// thread, each streamed to 8 batch copies (16 STG.128 in flight).
__global__ void neighbour_kernel(float* __restrict__ out) {
    __shared__ int   s_sel[81];
    __shared__ float s_add[81];
    if (threadIdx.x < 81) {
        int j = threadIdx.x;
        int c = j % 3, m = j / 3;
        int d = (c == 0) ? (m / 9 - 1) : (c == 1) ? ((m / 3) % 3 - 1) : (m % 3 - 1);
        s_sel[j] = c;
        s_add[j] = (float)d;
    }
    __syncthreads();

    int gi = blockIdx.x * blockDim.x + threadIdx.x;
    if (gi >= PB_F4 / 2) return;
    int qbase = gi * 2;
    float4* pout = (float4*)(out + O_NBR);

    #pragma unroll
    for (int qq = 0; qq < 2; qq++) {
        int q = qbase + qq;
        int e0  = q * 4;
        int vox = e0 / 81;
        int j0  = e0 - vox * 81;
        int x = vox / (V * V);
        int r = vox - x * (V * V);
        int y = r / V;
        int z = r - y * V;
        int zn = z + 1, yn = y, xn = x;
        if (zn == V) { zn = 0; yn = y + 1; if (yn == V) { yn = 0; xn = x + 1; } }
        float c0[3] = { (float)x,  (float)y,  (float)z  };
        float c1[3] = { (float)xn, (float)yn, (float)zn };

        float4 vv;
        float* vp = &vv.x;
        #pragma unroll
        for (int u = 0; u < 4; u++) {
            int jk = j0 + u;
            bool w = jk >= 81;
            int jj = w ? jk - 81 : jk;
            vp[u] = (w ? c1[s_sel[jj]] : c0[s_sel[jj]]) + s_add[jj];
        }
        #pragma unroll
        for (int b = 0; b < B; b++) __stcs(&pout[q + (size_t)b * PB_F4], vv);
    }
}

// ---------------------------------------------------------------------------
extern "C" void kernel_launch(void* const* d_in, const int* in_sizes, int n_in,
                              void* d_out, int out_size) {
    const float* pts = (const float*)d_in[0];
    float* out = (float*)d_out;

    bin_kernel      <<<(B * N / 4 + 255) / 256, 256>>>(pts);
    scan_kernel     <<<NTILES_TOT, 256>>>(out);
    scatter_kernel  <<<(B * N / 4 + 255) / 256, 256>>>();
    fixup_kernel    <<<(B * NBINS + 255) / 256, 256>>>();
    write_kernel    <<<(B * N / 4 + 255) / 256, 256>>>(out);
    neighbour_kernel<<<(PB_F4 / 2 + 255) / 256, 256>>>(out);
}

// round 11
// speedup vs baseline: 1.9123x; 1.9123x over previous
#include <cuda_runtime.h>
#include <cstdint>

#define B 8
#define N 100000
#define V 40
#define NBINS 64000
#define NTILES 63
#define TILE 1024
#define PB_F4 1296000                // float4s per batch in nbr table

// Output layout (float32 elements)
#define O_IDX  0
#define O_HASH 800000
#define O_NBR  1600000
#define O_MASK 43072000

// ---- scratch ----
__device__ int g_voxel[B * N];       // bin id per point
__device__ int g_rank[B * N];        // rank within bin (from histogram atomic)
__device__ int g_hist[B * NBINS];    // counts -> offsets; re-zeroed in finalize
__device__ int g_cursor[B * NBINS];  // offsets copy (finalize segment bounds)
__device__ int g_sorted[B * N];
__device__ int g_tsum[B * NTILES];

// ---------------------------------------------------------------------------
// bin: 4 points/thread via float4 loads; atomicAdd returns rank-in-bin.
__global__ void bin_kernel(const float* __restrict__ pts) {
    int gi = blockIdx.x * blockDim.x + threadIdx.x;
    if (gi >= (B * N) / 4) return;
    const float4* p4 = (const float4*)pts;
    float4 f0 = __ldg(&p4[3 * gi]);
    float4 f1 = __ldg(&p4[3 * gi + 1]);
    float4 f2 = __ldg(&p4[3 * gi + 2]);
    int b = gi / (N / 4);
    float px[4] = { f0.x, f0.w, f1.z, f2.y };
    float py[4] = { f0.y, f1.x, f1.w, f2.z };
    float pz[4] = { f0.z, f1.y, f2.x, f2.w };
    int bins[4], rnk[4];
    #pragma unroll
    for (int k = 0; k < 4; k++) {
        int cx = (int)(px[k] * (float)(V - 1));
        int cy = (int)(py[k] * (float)(V - 1));
        int cz = (int)(pz[k] * (float)(V - 1));
        bins[k] = cx * (V * V) + cy * V + cz;
    }
    #pragma unroll
    for (int k = 0; k < 4; k++)
        rnk[k] = atomicAdd(&g_hist[b * NBINS + bins[k]], 1);
    *(int4*)(g_voxel + 4 * gi) = make_int4(bins[0], bins[1], bins[2], bins[3]);
    *(int4*)(g_rank  + 4 * gi) = make_int4(rnk[0],  rnk[1],  rnk[2],  rnk[3]);
}

// ---- 3-phase scan (the R2 structure that coexisted with nbr overlap) ------
__global__ void scanA_kernel() {
    int b = blockIdx.x / NTILES;
    int t = blockIdx.x % NTILES;
    int tb = t * TILE + threadIdx.x * 4;
    int s = 0;
    if (tb < NBINS) {
        int4 v = *(const int4*)(g_hist + b * NBINS + tb);
        s = v.x + v.y + v.z + v.w;
    }
    #pragma unroll
    for (int o = 16; o > 0; o >>= 1) s += __shfl_down_sync(0xFFFFFFFFu, s, o);
    __shared__ int ws[8];
    int lane = threadIdx.x & 31, warp = threadIdx.x >> 5;
    if (lane == 0) ws[warp] = s;
    __syncthreads();
    if (threadIdx.x == 0) {
        int tot = 0;
        #pragma unroll
        for (int w = 0; w < 8; w++) tot += ws[w];
        g_tsum[blockIdx.x] = tot;
    }
}

__global__ void scanB_kernel() {
    int w = threadIdx.x >> 5, lane = threadIdx.x & 31;
    if (w >= B) return;
    int* ts = g_tsum + w * NTILES;
    int v0 = ts[lane];
    int v1 = (lane < NTILES - 32) ? ts[32 + lane] : 0;
    int s0 = v0, s1 = v1;
    #pragma unroll
    for (int o = 1; o < 32; o <<= 1) {
        int t0 = __shfl_up_sync(0xFFFFFFFFu, s0, o);
        int t1 = __shfl_up_sync(0xFFFFFFFFu, s1, o);
        if (lane >= o) { s0 += t0; s1 += t1; }
    }
    int tot0 = __shfl_sync(0xFFFFFFFFu, s0, 31);
    ts[lane] = s0 - v0;
    if (lane < NTILES - 32) ts[32 + lane] = tot0 + s1 - v1;
}

// scanC: offsets + cursors + mask (counts & offsets already in registers).
__global__ void scanC_kernel(float* __restrict__ out) {
    int b = blockIdx.x / NTILES;
    int t = blockIdx.x % NTILES;
    int tb = t * TILE + threadIdx.x * 4;
    int4 v = make_int4(0, 0, 0, 0);
    if (tb < NBINS) v = *(const int4*)(g_hist + b * NBINS + tb);
    int tsum = v.x + v.y + v.z + v.w;
    int lane = threadIdx.x & 31, warp = threadIdx.x >> 5;
    int x = tsum;
    #pragma unroll
    for (int o = 1; o < 32; o <<= 1) {
        int tt = __shfl_up_sync(0xFFFFFFFFu, x, o);
        if (lane >= o) x += tt;
    }
    __shared__ int ws[8];
    if (lane == 31) ws[warp] = x;
    __syncthreads();
    int woff = 0;
    #pragma unroll
    for (int w = 0; w < 8; w++) woff += (w < warp) ? ws[w] : 0;
    int base = g_tsum[blockIdx.x] + woff + x - tsum;
    if (tb < NBINS) {
        int4 o4;
        o4.x = base;
        o4.y = base + v.x;
        o4.z = base + v.x + v.y;
        o4.w = base + v.x + v.y + v.z;
        *(int4*)(g_hist   + b * NBINS + tb) = o4;
        *(int4*)(g_cursor + b * NBINS + tb) = o4;
        float4 m4;
        m4.x = (v.x > 0 && o4.x + v.x < N) ? 1.0f : 0.0f;
        m4.y = (v.y > 0 && o4.y + v.y < N) ? 1.0f : 0.0f;
        m4.z = (v.z > 0 && o4.z + v.z < N) ? 1.0f : 0.0f;
        m4.w = (v.w > 0 && o4.w + v.w < N) ? 1.0f : 0.0f;
        *(float4*)(out + O_MASK + b * NBINS + tb) = m4;
    }
}

// ---------------------------------------------------------------------------
// scatter: NO atomics. pos = offset[bin] + rank.
__global__ void scatter_kernel() {
    int gi = blockIdx.x * blockDim.x + threadIdx.x;
    if (gi >= (B * N) / 4) return;
    int i0 = gi * 4;
    int b = gi / (N / 4);
    int4 vb = *(const int4*)(g_voxel + i0);
    int4 rb = *(const int4*)(g_rank  + i0);
    int bins[4] = { vb.x, vb.y, vb.z, vb.w };
    int rnk[4]  = { rb.x, rb.y, rb.z, rb.w };
    int pos[4];
    #pragma unroll
    for (int k = 0; k < 4; k++)
        pos[k] = g_hist[b * NBINS + bins[k]] + rnk[k];
    int nbase = i0 - b * N;
    #pragma unroll
    for (int k = 0; k < 4; k++)
        g_sorted[b * N + pos[k]] = nbase + k;
}

// ---------------------------------------------------------------------------
// finalize (R2 style): stable fixup (only count>=2) + idx/hash writes;
// re-zeroes g_hist for replay. Mask already written by scanC.
__global__ void finalize_kernel(float* __restrict__ out) {
    int t = blockIdx.x * blockDim.x + threadIdx.x;
    if (t >= B * NBINS) return;
    int b = t / NBINS;
    int bin = t - b * NBINS;
    int s = g_cursor[t];
    int e = (bin == NBINS - 1) ? N : g_cursor[t + 1];
    g_hist[t] = 0;                        // restore count invariant for replay
    if (e == s) return;
    int* seg = g_sorted + b * N;

    if (e - s >= 2) {
        for (int a = s + 1; a < e; a++) {
            int key = seg[a];
            int j = a - 1;
            while (j >= s && seg[j] > key) { seg[j + 1] = seg[j]; j--; }
            seg[j + 1] = key;
        }
    }

    int cx = bin / (V * V);
    int cy = (bin / V) % V;
    int cz = bin % V;
    float h = (float)(cx * 10000 + cy * 100 + cz);
    for (int j = s; j < e; j++) {
        out[O_IDX  + b * N + j] = (float)seg[j];
        out[O_HASH + b * N + j] = h;
    }
}

// ---------------------------------------------------------------------------
// neighbour table (R2's version verbatim): one thread = one float4,
// streamed to 8 batch copies.
__global__ void neighbour_kernel(float* __restrict__ out) {
    __shared__ int   s_sel[81];
    __shared__ float s_add[81];
    if (threadIdx.x < 81) {
        int j = threadIdx.x;
        int c = j % 3, m = j / 3;
        int d = (c == 0) ? (m / 9 - 1) : (c == 1) ? ((m / 3) % 3 - 1) : (m % 3 - 1);
        s_sel[j] = c;
        s_add[j] = (float)d;
    }
    __syncthreads();

    int q = blockIdx.x * blockDim.x + threadIdx.x;
    if (q >= PB_F4) return;

    int e0  = q * 4;
    int vox = e0 / 81;
    int j0  = e0 - vox * 81;
    int x = vox / (V * V);
    int r = vox - x * (V * V);
    int y = r / V;
    int z = r - y * V;
    int zn = z + 1, yn = y, xn = x;
    if (zn == V) { zn = 0; yn = y + 1; if (yn == V) { yn = 0; xn = x + 1; } }
    float xf = (float)x, yf = (float)y, zf = (float)z;
    float xf1 = (float)xn, yf1 = (float)yn, zf1 = (float)zn;

    float4 v;
    float* vp = &v.x;
    #pragma unroll
    for (int k = 0; k < 4; k++) {
        int jk = j0 + k;
        bool w = jk >= 81;
        int jj = w ? jk - 81 : jk;
        int sel = s_sel[jj];
        float cx = (sel == 0) ? (w ? xf1 : xf)
                 : (sel == 1) ? (w ? yf1 : yf)
                              : (w ? zf1 : zf);
        vp[k] = cx + s_add[jj];
    }

    float4* pout = (float4*)(out + O_NBR);
    #pragma unroll
    for (int b = 0; b < B; b++) pout[q + b * PB_F4] = v;
}

// ---------------------------------------------------------------------------
extern "C" void kernel_launch(void* const* d_in, const int* in_sizes, int n_in,
                              void* d_out, int out_size) {
    const float* pts = (const float*)d_in[0];
    float* out = (float*)d_out;

    static cudaStream_t s_side = nullptr;
    static cudaEvent_t ev_fork = nullptr, ev_join = nullptr;
    if (s_side == nullptr) {
        cudaStreamCreateWithFlags(&s_side, cudaStreamNonBlocking);
        cudaEventCreateWithFlags(&ev_fork, cudaEventDisableTiming);
        cudaEventCreateWithFlags(&ev_join, cudaEventDisableTiming);
    }

    // Fork: neighbour table on the side stream (identical to R2).
    cudaEventRecord(ev_fork, 0);
    cudaStreamWaitEvent(s_side, ev_fork, 0);
    neighbour_kernel<<<(PB_F4 + 255) / 256, 256, 0, s_side>>>(out);
    cudaEventRecord(ev_join, s_side);

    // Main chain on the default stream.
    bin_kernel     <<<(B * N / 4 + 255) / 256, 256>>>(pts);
    scanA_kernel   <<<B * NTILES, 256>>>();
    scanB_kernel   <<<1, 256>>>();
    scanC_kernel   <<<B * NTILES, 256>>>(out);
    scatter_kernel <<<(B * N / 4 + 255) / 256, 256>>>();
    finalize_kernel<<<(B * NBINS + 255) / 256, 256>>>(out);

    // Join.
    cudaStreamWaitEvent(0, ev_join, 0);
}

// round 12
// speedup vs baseline: 2.0307x; 1.0620x over previous
#include <cuda_runtime.h>
#include <cstdint>

#define B 8
#define N 100000
#define V 40
#define NBINS 64000
#define NTILES 63
#define TILE 1024
#define PB_F4 1296000                // float4s per batch in nbr table

// Output layout (float32 elements)
#define O_IDX  0
#define O_HASH 800000
#define O_NBR  1600000
#define O_MASK 43072000

// ---- scratch ----
__device__ int g_voxel[B * N];       // bin id per point
__device__ int g_rank[B * N];        // rank within bin (from histogram atomic)
__device__ int g_hist[B * NBINS];    // counts -> offsets; re-zeroed in finalize
__device__ int g_cursor[B * NBINS];  // offsets copy (finalize segment bounds)
__device__ int g_sorted[B * N];
__device__ int g_tsum[B * NTILES];

// ---------------------------------------------------------------------------
// bin: 4 points/thread via float4 loads; atomicAdd returns rank-in-bin.
__global__ void bin_kernel(const float* __restrict__ pts) {
    int gi = blockIdx.x * blockDim.x + threadIdx.x;
    if (gi >= (B * N) / 4) return;
    const float4* p4 = (const float4*)pts;
    float4 f0 = __ldg(&p4[3 * gi]);
    float4 f1 = __ldg(&p4[3 * gi + 1]);
    float4 f2 = __ldg(&p4[3 * gi + 2]);
    int b = gi / (N / 4);
    float px[4] = { f0.x, f0.w, f1.z, f2.y };
    float py[4] = { f0.y, f1.x, f1.w, f2.z };
    float pz[4] = { f0.z, f1.y, f2.x, f2.w };
    int bins[4], rnk[4];
    #pragma unroll
    for (int k = 0; k < 4; k++) {
        int cx = (int)(px[k] * (float)(V - 1));
        int cy = (int)(py[k] * (float)(V - 1));
        int cz = (int)(pz[k] * (float)(V - 1));
        bins[k] = cx * (V * V) + cy * V + cz;
    }
    #pragma unroll
    for (int k = 0; k < 4; k++)
        rnk[k] = atomicAdd(&g_hist[b * NBINS + bins[k]], 1);
    *(int4*)(g_voxel + 4 * gi) = make_int4(bins[0], bins[1], bins[2], bins[3]);
    *(int4*)(g_rank  + 4 * gi) = make_int4(rnk[0],  rnk[1],  rnk[2],  rnk[3]);
}

// ---- 3-phase scan ----------------------------------------------------------
__global__ void scanA_kernel() {
    int b = blockIdx.x / NTILES;
    int t = blockIdx.x % NTILES;
    int tb = t * TILE + threadIdx.x * 4;
    int s = 0;
    if (tb < NBINS) {
        int4 v = *(const int4*)(g_hist + b * NBINS + tb);
        s = v.x + v.y + v.z + v.w;
    }
    #pragma unroll
    for (int o = 16; o > 0; o >>= 1) s += __shfl_down_sync(0xFFFFFFFFu, s, o);
    __shared__ int ws[8];
    int lane = threadIdx.x & 31, warp = threadIdx.x >> 5;
    if (lane == 0) ws[warp] = s;
    __syncthreads();
    if (threadIdx.x == 0) {
        int tot = 0;
        #pragma unroll
        for (int w = 0; w < 8; w++) tot += ws[w];
        g_tsum[blockIdx.x] = tot;
    }
}

__global__ void scanB_kernel() {
    int w = threadIdx.x >> 5, lane = threadIdx.x & 31;
    if (w >= B) return;
    int* ts = g_tsum + w * NTILES;
    int v0 = ts[lane];
    int v1 = (lane < NTILES - 32) ? ts[32 + lane] : 0;
    int s0 = v0, s1 = v1;
    #pragma unroll
    for (int o = 1; o < 32; o <<= 1) {
        int t0 = __shfl_up_sync(0xFFFFFFFFu, s0, o);
        int t1 = __shfl_up_sync(0xFFFFFFFFu, s1, o);
        if (lane >= o) { s0 += t0; s1 += t1; }
    }
    int tot0 = __shfl_sync(0xFFFFFFFFu, s0, 31);
    ts[lane] = s0 - v0;
    if (lane < NTILES - 32) ts[32 + lane] = tot0 + s1 - v1;
}

// scanC: offsets + cursors + mask.
__global__ void scanC_kernel(float* __restrict__ out) {
    int b = blockIdx.x / NTILES;
    int t = blockIdx.x % NTILES;
    int tb = t * TILE + threadIdx.x * 4;
    int4 v = make_int4(0, 0, 0, 0);
    if (tb < NBINS) v = *(const int4*)(g_hist + b * NBINS + tb);
    int tsum = v.x + v.y + v.z + v.w;
    int lane = threadIdx.x & 31, warp = threadIdx.x >> 5;
    int x = tsum;
    #pragma unroll
    for (int o = 1; o < 32; o <<= 1) {
        int tt = __shfl_up_sync(0xFFFFFFFFu, x, o);
        if (lane >= o) x += tt;
    }
    __shared__ int ws[8];
    if (lane == 31) ws[warp] = x;
    __syncthreads();
    int woff = 0;
    #pragma unroll
    for (int w = 0; w < 8; w++) woff += (w < warp) ? ws[w] : 0;
    int base = g_tsum[blockIdx.x] + woff + x - tsum;
    if (tb < NBINS) {
        int4 o4;
        o4.x = base;
        o4.y = base + v.x;
        o4.z = base + v.x + v.y;
        o4.w = base + v.x + v.y + v.z;
        *(int4*)(g_hist   + b * NBINS + tb) = o4;
        *(int4*)(g_cursor + b * NBINS + tb) = o4;
        float4 m4;
        m4.x = (v.x > 0 && o4.x + v.x < N) ? 1.0f : 0.0f;
        m4.y = (v.y > 0 && o4.y + v.y < N) ? 1.0f : 0.0f;
        m4.z = (v.z > 0 && o4.z + v.z < N) ? 1.0f : 0.0f;
        m4.w = (v.w > 0 && o4.w + v.w < N) ? 1.0f : 0.0f;
        *(float4*)(out + O_MASK + b * NBINS + tb) = m4;
    }
}

// ---------------------------------------------------------------------------
// scatter: NO atomics. pos = offset[bin] + rank.
__global__ void scatter_kernel() {
    int gi = blockIdx.x * blockDim.x + threadIdx.x;
    if (gi >= (B * N) / 4) return;
    int i0 = gi * 4;
    int b = gi / (N / 4);
    int4 vb = *(const int4*)(g_voxel + i0);
    int4 rb = *(const int4*)(g_rank  + i0);
    int bins[4] = { vb.x, vb.y, vb.z, vb.w };
    int rnk[4]  = { rb.x, rb.y, rb.z, rb.w };
    int pos[4];
    #pragma unroll
    for (int k = 0; k < 4; k++)
        pos[k] = g_hist[b * NBINS + bins[k]] + rnk[k];
    int nbase = i0 - b * N;
    #pragma unroll
    for (int k = 0; k < 4; k++)
        g_sorted[b * N + pos[k]] = nbase + k;
}

// ---------------------------------------------------------------------------
// finalize: stable fixup (count>=2 only) + idx/hash writes; re-zeroes g_hist.
__global__ void finalize_kernel(float* __restrict__ out) {
    int t = blockIdx.x * blockDim.x + threadIdx.x;
    if (t >= B * NBINS) return;
    int b = t / NBINS;
    int bin = t - b * NBINS;
    int s = g_cursor[t];
    int e = (bin == NBINS - 1) ? N : g_cursor[t + 1];
    g_hist[t] = 0;                        // restore count invariant for replay
    if (e == s) return;
    int* seg = g_sorted + b * N;

    if (e - s >= 2) {
        for (int a = s + 1; a < e; a++) {
            int key = seg[a];
            int j = a - 1;
            while (j >= s && seg[j] > key) { seg[j + 1] = seg[j]; j--; }
            seg[j + 1] = key;
        }
    }

    int cx = bin / (V * V);
    int cy = (bin / V) % V;
    int cz = bin % V;
    float h = (float)(cx * 10000 + cy * 100 + cz);
    for (int j = s; j < e; j++) {
        out[O_IDX  + b * N + j] = (float)seg[j];
        out[O_HASH + b * N + j] = h;
    }
}

// ---------------------------------------------------------------------------
// neighbour table: one thread = one float4, streamed to 8 batch copies.
__global__ void neighbour_kernel(float* __restrict__ out) {
    __shared__ int   s_sel[81];
    __shared__ float s_add[81];
    if (threadIdx.x < 81) {
        int j = threadIdx.x;
        int c = j % 3, m = j / 3;
        int d = (c == 0) ? (m / 9 - 1) : (c == 1) ? ((m / 3) % 3 - 1) : (m % 3 - 1);
        s_sel[j] = c;
        s_add[j] = (float)d;
    }
    __syncthreads();

    int q = blockIdx.x * blockDim.x + threadIdx.x;
    if (q >= PB_F4) return;

    int e0  = q * 4;
    int vox = e0 / 81;
    int j0  = e0 - vox * 81;
    int x = vox / (V * V);
    int r = vox - x * (V * V);
    int y = r / V;
    int z = r - y * V;
    int zn = z + 1, yn = y, xn = x;
    if (zn == V) { zn = 0; yn = y + 1; if (yn == V) { yn = 0; xn = x + 1; } }
    float xf = (float)x, yf = (float)y, zf = (float)z;
    float xf1 = (float)xn, yf1 = (float)yn, zf1 = (float)zn;

    float4 v;
    float* vp = &v.x;
    #pragma unroll
    for (int k = 0; k < 4; k++) {
        int jk = j0 + k;
        bool w = jk >= 81;
        int jj = w ? jk - 81 : jk;
        int sel = s_sel[jj];
        float cx = (sel == 0) ? (w ? xf1 : xf)
                 : (sel == 1) ? (w ? yf1 : yf)
                              : (w ? zf1 : zf);
        vp[k] = cx + s_add[jj];
    }

    float4* pout = (float4*)(out + O_NBR);
    #pragma unroll
    for (int b = 0; b < B; b++) __stcs(&pout[q + (size_t)b * PB_F4], v);
}

// ---------------------------------------------------------------------------
extern "C" void kernel_launch(void* const* d_in, const int* in_sizes, int n_in,
                              void* d_out, int out_size) {
    const float* pts = (const float*)d_in[0];
    float* out = (float*)d_out;

    static cudaStream_t s_chain = nullptr, s_nbr = nullptr;
    static cudaEvent_t ev_fork = nullptr, ev_a = nullptr, ev_b = nullptr;
    if (s_chain == nullptr) {
        int lo = 0, hi = 0;
        cudaDeviceGetStreamPriorityRange(&lo, &hi);   // hi = greatest priority
        cudaStreamCreateWithPriority(&s_chain, cudaStreamNonBlocking, hi);
        cudaStreamCreateWithPriority(&s_nbr,   cudaStreamNonBlocking, lo);
        cudaEventCreateWithFlags(&ev_fork, cudaEventDisableTiming);
        cudaEventCreateWithFlags(&ev_a,    cudaEventDisableTiming);
        cudaEventCreateWithFlags(&ev_b,    cudaEventDisableTiming);
    }

    // fork from legacy stream
    cudaEventRecord(ev_fork, 0);
    cudaStreamWaitEvent(s_nbr,   ev_fork, 0);
    cudaStreamWaitEvent(s_chain, ev_fork, 0);

    // LOW priority: neighbour table (big block backlog, store-BW bound)
    neighbour_kernel<<<(PB_F4 + 255) / 256, 256, 0, s_nbr>>>(out);
    cudaEventRecord(ev_b, s_nbr);

    // HIGH priority: sort chain (latency bound; blocks get dispatch preference)
    bin_kernel     <<<(B * N / 4 + 255) / 256, 256, 0, s_chain>>>(pts);
    scanA_kernel   <<<B * NTILES, 256, 0, s_chain>>>();
    scanB_kernel   <<<1, 256, 0, s_chain>>>();
    scanC_kernel   <<<B * NTILES, 256, 0, s_chain>>>(out);
    scatter_kernel <<<(B * N / 4 + 255) / 256, 256, 0, s_chain>>>();
    finalize_kernel<<<(B * NBINS + 255) / 256, 256, 0, s_chain>>>(out);
    cudaEventRecord(ev_a, s_chain);

    // join to legacy stream
    cudaStreamWaitEvent(0, ev_a, 0);
    cudaStreamWaitEvent(0, ev_b, 0);
}

// round 13
// speedup vs baseline: 2.0951x; 1.0317x over previous
#include <cuda_runtime.h>
#include <cstdint>

#define B 8
#define N 100000
#define V 40
#define NBINS 64000
#define NTILES 63
#define TILE 1024
#define PB_F4 1296000                // float4s per batch in nbr table

// Output layout (float32 elements)
#define O_IDX  0
#define O_HASH 800000
#define O_NBR  1600000
#define O_MASK 43072000

// ---- scratch ----
__device__ int g_voxel[B * N];       // bin id per point
__device__ int g_rank[B * N];        // rank within bin (from histogram atomic)
__device__ int g_hist[B * NBINS];    // counts -> offsets; re-zeroed in finalize
__device__ int g_cursor[B * NBINS];  // offsets copy (finalize segment bounds)
__device__ int g_sorted[B * N];
__device__ int g_tsum[B * NTILES];

// ---------------------------------------------------------------------------
// bin: 4 points/thread via float4 loads; atomicAdd returns rank-in-bin.
__global__ void bin_kernel(const float* __restrict__ pts) {
    int gi = blockIdx.x * blockDim.x + threadIdx.x;
    if (gi >= (B * N) / 4) return;
    const float4* p4 = (const float4*)pts;
    float4 f0 = __ldg(&p4[3 * gi]);
    float4 f1 = __ldg(&p4[3 * gi + 1]);
    float4 f2 = __ldg(&p4[3 * gi + 2]);
    int b = gi / (N / 4);
    float px[4] = { f0.x, f0.w, f1.z, f2.y };
    float py[4] = { f0.y, f1.x, f1.w, f2.z };
    float pz[4] = { f0.z, f1.y, f2.x, f2.w };
    int bins[4], rnk[4];
    #pragma unroll
    for (int k = 0; k < 4; k++) {
        int cx = (int)(px[k] * (float)(V - 1));
        int cy = (int)(py[k] * (float)(V - 1));
        int cz = (int)(pz[k] * (float)(V - 1));
        bins[k] = cx * (V * V) + cy * V + cz;
    }
    #pragma unroll
    for (int k = 0; k < 4; k++)
        rnk[k] = atomicAdd(&g_hist[b * NBINS + bins[k]], 1);
    *(int4*)(g_voxel + 4 * gi) = make_int4(bins[0], bins[1], bins[2], bins[3]);
    *(int4*)(g_rank  + 4 * gi) = make_int4(rnk[0],  rnk[1],  rnk[2],  rnk[3]);
}

// ---- 2-phase scan: scanA tile sums; scanC computes its own base ------------
__global__ void scanA_kernel() {
    int b = blockIdx.x / NTILES;
    int t = blockIdx.x % NTILES;
    int tb = t * TILE + threadIdx.x * 4;
    int s = 0;
    if (tb < NBINS) {
        int4 v = *(const int4*)(g_hist + b * NBINS + tb);
        s = v.x + v.y + v.z + v.w;
    }
    #pragma unroll
    for (int o = 16; o > 0; o >>= 1) s += __shfl_down_sync(0xFFFFFFFFu, s, o);
    __shared__ int ws[8];
    int lane = threadIdx.x & 31, warp = threadIdx.x >> 5;
    if (lane == 0) ws[warp] = s;
    __syncthreads();
    if (threadIdx.x == 0) {
        int tot = 0;
        #pragma unroll
        for (int w = 0; w < 8; w++) tot += ws[w];
        g_tsum[blockIdx.x] = tot;
    }
}

// scanC: warp 0 sums preceding tile sums for the base; block scans its tile;
// writes offsets + cursors + mask.
__global__ void scanC_kernel(float* __restrict__ out) {
    int b = blockIdx.x / NTILES;
    int t = blockIdx.x % NTILES;
    int tid = threadIdx.x;
    __shared__ int ws[8];
    __shared__ int s_base;

    // tile base: sum of the t preceding tile sums (one warp, L2-hot)
    if (tid < 32) {
        int v = 0;
        if (tid < t)      v += g_tsum[b * NTILES + tid];
        if (tid + 32 < t) v += g_tsum[b * NTILES + tid + 32];
        #pragma unroll
        for (int o = 16; o > 0; o >>= 1) v += __shfl_down_sync(0xFFFFFFFFu, v, o);
        if (tid == 0) s_base = v;
    }

    int tb = t * TILE + tid * 4;
    int4 v = make_int4(0, 0, 0, 0);
    if (tb < NBINS) v = *(const int4*)(g_hist + b * NBINS + tb);
    int tsum = v.x + v.y + v.z + v.w;
    int lane = tid & 31, warp = tid >> 5;
    int x = tsum;
    #pragma unroll
    for (int o = 1; o < 32; o <<= 1) {
        int tt = __shfl_up_sync(0xFFFFFFFFu, x, o);
        if (lane >= o) x += tt;
    }
    if (lane == 31) ws[warp] = x;
    __syncthreads();
    int woff = 0;
    #pragma unroll
    for (int w = 0; w < 8; w++) woff += (w < warp) ? ws[w] : 0;
    int base = s_base + woff + x - tsum;
    if (tb < NBINS) {
        int4 o4;
        o4.x = base;
        o4.y = base + v.x;
        o4.z = base + v.x + v.y;
        o4.w = base + v.x + v.y + v.z;
        *(int4*)(g_hist   + b * NBINS + tb) = o4;
        *(int4*)(g_cursor + b * NBINS + tb) = o4;
        float4 m4;
        m4.x = (v.x > 0 && o4.x + v.x < N) ? 1.0f : 0.0f;
        m4.y = (v.y > 0 && o4.y + v.y < N) ? 1.0f : 0.0f;
        m4.z = (v.z > 0 && o4.z + v.z < N) ? 1.0f : 0.0f;
        m4.w = (v.w > 0 && o4.w + v.w < N) ? 1.0f : 0.0f;
        *(float4*)(out + O_MASK + b * NBINS + tb) = m4;
    }
}

// ---------------------------------------------------------------------------
// scatter: NO atomics. pos = offset[bin] + rank.
__global__ void scatter_kernel() {
    int gi = blockIdx.x * blockDim.x + threadIdx.x;
    if (gi >= (B * N) / 4) return;
    int i0 = gi * 4;
    int b = gi / (N / 4);
    int4 vb = *(const int4*)(g_voxel + i0);
    int4 rb = *(const int4*)(g_rank  + i0);
    int bins[4] = { vb.x, vb.y, vb.z, vb.w };
    int rnk[4]  = { rb.x, rb.y, rb.z, rb.w };
    int pos[4];
    #pragma unroll
    for (int k = 0; k < 4; k++)
        pos[k] = g_hist[b * NBINS + bins[k]] + rnk[k];
    int nbase = i0 - b * N;
    #pragma unroll
    for (int k = 0; k < 4; k++)
        g_sorted[b * N + pos[k]] = nbase + k;
}

// ---------------------------------------------------------------------------
// finalize: stable fixup (count>=2 only) + idx/hash writes; re-zeroes g_hist.
__global__ void finalize_kernel(float* __restrict__ out) {
    int t = blockIdx.x * blockDim.x + threadIdx.x;
    if (t >= B * NBINS) return;
    int b = t / NBINS;
    int bin = t - b * NBINS;
    int s = g_cursor[t];
    int e = (bin == NBINS - 1) ? N : g_cursor[t + 1];
    g_hist[t] = 0;                        // restore count invariant for replay
    if (e == s) return;
    int* seg = g_sorted + b * N;

    if (e - s >= 2) {
        for (int a = s + 1; a < e; a++) {
            int key = seg[a];
            int j = a - 1;
            while (j >= s && seg[j] > key) { seg[j + 1] = seg[j]; j--; }
            seg[j + 1] = key;
        }
    }

    int cx = bin / (V * V);
    int cy = (bin / V) % V;
    int cz = bin % V;
    float h = (float)(cx * 10000 + cy * 100 + cz);
    for (int j = s; j < e; j++) {
        out[O_IDX  + b * N + j] = (float)seg[j];
        out[O_HASH + b * N + j] = h;
    }
}

// ---------------------------------------------------------------------------
// neighbour table: one thread = one float4, streamed to 8 batch copies.
__global__ void neighbour_kernel(float* __restrict__ out) {
    __shared__ int   s_sel[81];
    __shared__ float s_add[81];
    if (threadIdx.x < 81) {
        int j = threadIdx.x;
        int c = j % 3, m = j / 3;
        int d = (c == 0) ? (m / 9 - 1) : (c == 1) ? ((m / 3) % 3 - 1) : (m % 3 - 1);
        s_sel[j] = c;
        s_add[j] = (float)d;
    }
    __syncthreads();

    int q = blockIdx.x * blockDim.x + threadIdx.x;
    if (q >= PB_F4) return;

    int e0  = q * 4;
    int vox = e0 / 81;
    int j0  = e0 - vox * 81;
    int x = vox / (V * V);
    int r = vox - x * (V * V);
    int y = r / V;
    int z = r - y * V;
    int zn = z + 1, yn = y, xn = x;
    if (zn == V) { zn = 0; yn = y + 1; if (yn == V) { yn = 0; xn = x + 1; } }
    float xf = (float)x, yf = (float)y, zf = (float)z;
    float xf1 = (float)xn, yf1 = (float)yn, zf1 = (float)zn;

    float4 v;
    float* vp = &v.x;
    #pragma unroll
    for (int k = 0; k < 4; k++) {
        int jk = j0 + k;
        bool w = jk >= 81;
        int jj = w ? jk - 81 : jk;
        int sel = s_sel[jj];
        float cx = (sel == 0) ? (w ? xf1 : xf)
                 : (sel == 1) ? (w ? yf1 : yf)
                              : (w ? zf1 : zf);
        vp[k] = cx + s_add[jj];
    }

    float4* pout = (float4*)(out + O_NBR);
    #pragma unroll
    for (int b = 0; b < B; b++) __stcs(&pout[q + (size_t)b * PB_F4], v);
}

// ---------------------------------------------------------------------------
extern "C" void kernel_launch(void* const* d_in, const int* in_sizes, int n_in,
                              void* d_out, int out_size) {
    const float* pts = (const float*)d_in[0];
    float* out = (float*)d_out;

    static cudaStream_t s_chain = nullptr, s_nbr = nullptr;
    static cudaEvent_t ev_fork = nullptr, ev_a = nullptr, ev_b = nullptr;
    if (s_chain == nullptr) {
        int lo = 0, hi = 0;
        cudaDeviceGetStreamPriorityRange(&lo, &hi);   // hi = greatest priority
        cudaStreamCreateWithPriority(&s_chain, cudaStreamNonBlocking, hi);
        cudaStreamCreateWithPriority(&s_nbr,   cudaStreamNonBlocking, lo);
        cudaEventCreateWithFlags(&ev_fork, cudaEventDisableTiming);
        cudaEventCreateWithFlags(&ev_a,    cudaEventDisableTiming);
        cudaEventCreateWithFlags(&ev_b,    cudaEventDisableTiming);
    }

    // fork from legacy stream
    cudaEventRecord(ev_fork, 0);
    cudaStreamWaitEvent(s_nbr,   ev_fork, 0);
    cudaStreamWaitEvent(s_chain, ev_fork, 0);

    // LOW priority: neighbour table (big block backlog, store-BW bound)
    neighbour_kernel<<<(PB_F4 + 255) / 256, 256, 0, s_nbr>>>(out);
    cudaEventRecord(ev_b, s_nbr);

    // HIGH priority: sort chain (latency bound; blocks get dispatch preference)
    bin_kernel     <<<(B * N / 4 + 255) / 256, 256, 0, s_chain>>>(pts);
    scanA_kernel   <<<B * NTILES, 256, 0, s_chain>>>();
    scanC_kernel   <<<B * NTILES, 256, 0, s_chain>>>(out);
    scatter_kernel <<<(B * N / 4 + 255) / 256, 256, 0, s_chain>>>();
    finalize_kernel<<<(B * NBINS + 255) / 256, 256, 0, s_chain>>>(out);
    cudaEventRecord(ev_a, s_chain);

    // join to legacy stream
    cudaStreamWaitEvent(0, ev_a, 0);
    cudaStreamWaitEvent(0, ev_b, 0);
}

// round 14
// speedup vs baseline: 2.1660x; 1.0338x over previous
#include <cuda_runtime.h>
#include <cstdint>

#define B 8
#define N 100000
#define V 40
#define NBINS 64000
#define NTILES 63
#define TILE 1024
#define PB_F4 1296000                // float4s per batch in nbr table

// Output layout (float32 elements)
#define O_IDX  0
#define O_HASH 800000
#define O_NBR  1600000
#define O_MASK 43072000

#define NBR_BLOCKS 296               // 2 per SM — leaves ~75% occupancy for chain
#define NBR_THREADS 256

// ---- scratch ----
__device__ int g_voxel[B * N];       // bin id per point
__device__ int g_rank[B * N];        // rank within bin (from histogram atomic)
__device__ int g_hist[B * NBINS];    // counts -> offsets; re-zeroed in finalize
__device__ int g_cursor[B * NBINS];  // offsets copy (finalize segment bounds)
__device__ int g_sorted[B * N];
__device__ int g_tsum[B * NTILES];

// ---------------------------------------------------------------------------
// bin: 4 points/thread via float4 loads; atomicAdd returns rank-in-bin.
__global__ void bin_kernel(const float* __restrict__ pts) {
    int gi = blockIdx.x * blockDim.x + threadIdx.x;
    if (gi >= (B * N) / 4) return;
    const float4* p4 = (const float4*)pts;
    float4 f0 = __ldg(&p4[3 * gi]);
    float4 f1 = __ldg(&p4[3 * gi + 1]);
    float4 f2 = __ldg(&p4[3 * gi + 2]);
    int b = gi / (N / 4);
    float px[4] = { f0.x, f0.w, f1.z, f2.y };
    float py[4] = { f0.y, f1.x, f1.w, f2.z };
    float pz[4] = { f0.z, f1.y, f2.x, f2.w };
    int bins[4], rnk[4];
    #pragma unroll
    for (int k = 0; k < 4; k++) {
        int cx = (int)(px[k] * (float)(V - 1));
        int cy = (int)(py[k] * (float)(V - 1));
        int cz = (int)(pz[k] * (float)(V - 1));
        bins[k] = cx * (V * V) + cy * V + cz;
    }
    #pragma unroll
    for (int k = 0; k < 4; k++)
        rnk[k] = atomicAdd(&g_hist[b * NBINS + bins[k]], 1);
    *(int4*)(g_voxel + 4 * gi) = make_int4(bins[0], bins[1], bins[2], bins[3]);
    *(int4*)(g_rank  + 4 * gi) = make_int4(rnk[0],  rnk[1],  rnk[2],  rnk[3]);
}

// ---- 2-phase scan: scanA tile sums; scanC computes its own base ------------
__global__ void scanA_kernel() {
    int b = blockIdx.x / NTILES;
    int t = blockIdx.x % NTILES;
    int tb = t * TILE + threadIdx.x * 4;
    int s = 0;
    if (tb < NBINS) {
        int4 v = *(const int4*)(g_hist + b * NBINS + tb);
        s = v.x + v.y + v.z + v.w;
    }
    #pragma unroll
    for (int o = 16; o > 0; o >>= 1) s += __shfl_down_sync(0xFFFFFFFFu, s, o);
    __shared__ int ws[8];
    int lane = threadIdx.x & 31, warp = threadIdx.x >> 5;
    if (lane == 0) ws[warp] = s;
    __syncthreads();
    if (threadIdx.x == 0) {
        int tot = 0;
        #pragma unroll
        for (int w = 0; w < 8; w++) tot += ws[w];
        g_tsum[blockIdx.x] = tot;
    }
}

// scanC: warp 0 sums preceding tile sums for the base; block scans its tile;
// writes offsets + cursors + mask.
__global__ void scanC_kernel(float* __restrict__ out) {
    int b = blockIdx.x / NTILES;
    int t = blockIdx.x % NTILES;
    int tid = threadIdx.x;
    __shared__ int ws[8];
    __shared__ int s_base;

    if (tid < 32) {
        int v = 0;
        if (tid < t)      v += g_tsum[b * NTILES + tid];
        if (tid + 32 < t) v += g_tsum[b * NTILES + tid + 32];
        #pragma unroll
        for (int o = 16; o > 0; o >>= 1) v += __shfl_down_sync(0xFFFFFFFFu, v, o);
        if (tid == 0) s_base = v;
    }

    int tb = t * TILE + tid * 4;
    int4 v = make_int4(0, 0, 0, 0);
    if (tb < NBINS) v = *(const int4*)(g_hist + b * NBINS + tb);
    int tsum = v.x + v.y + v.z + v.w;
    int lane = tid & 31, warp = tid >> 5;
    int x = tsum;
    #pragma unroll
    for (int o = 1; o < 32; o <<= 1) {
        int tt = __shfl_up_sync(0xFFFFFFFFu, x, o);
        if (lane >= o) x += tt;
    }
    if (lane == 31) ws[warp] = x;
    __syncthreads();
    int woff = 0;
    #pragma unroll
    for (int w = 0; w < 8; w++) woff += (w < warp) ? ws[w] : 0;
    int base = s_base + woff + x - tsum;
    if (tb < NBINS) {
        int4 o4;
        o4.x = base;
        o4.y = base + v.x;
        o4.z = base + v.x + v.y;
        o4.w = base + v.x + v.y + v.z;
        *(int4*)(g_hist   + b * NBINS + tb) = o4;
        *(int4*)(g_cursor + b * NBINS + tb) = o4;
        float4 m4;
        m4.x = (v.x > 0 && o4.x + v.x < N) ? 1.0f : 0.0f;
        m4.y = (v.y > 0 && o4.y + v.y < N) ? 1.0f : 0.0f;
        m4.z = (v.z > 0 && o4.z + v.z < N) ? 1.0f : 0.0f;
        m4.w = (v.w > 0 && o4.w + v.w < N) ? 1.0f : 0.0f;
        *(float4*)(out + O_MASK + b * NBINS + tb) = m4;
    }
}

// ---------------------------------------------------------------------------
// scatter: NO atomics. pos = offset[bin] + rank.
__global__ void scatter_kernel() {
    int gi = blockIdx.x * blockDim.x + threadIdx.x;
    if (gi >= (B * N) / 4) return;
    int i0 = gi * 4;
    int b = gi / (N / 4);
    int4 vb = *(const int4*)(g_voxel + i0);
    int4 rb = *(const int4*)(g_rank  + i0);
    int bins[4] = { vb.x, vb.y, vb.z, vb.w };
    int rnk[4]  = { rb.x, rb.y, rb.z, rb.w };
    int pos[4];
    #pragma unroll
    for (int k = 0; k < 4; k++)
        pos[k] = g_hist[b * NBINS + bins[k]] + rnk[k];
    int nbase = i0 - b * N;
    #pragma unroll
    for (int k = 0; k < 4; k++)
        g_sorted[b * N + pos[k]] = nbase + k;
}

// ---------------------------------------------------------------------------
// finalize: stable fixup (count>=2 only) + idx/hash writes; re-zeroes g_hist.
__global__ void finalize_kernel(float* __restrict__ out) {
    int t = blockIdx.x * blockDim.x + threadIdx.x;
    if (t >= B * NBINS) return;
    int b = t / NBINS;
    int bin = t - b * NBINS;
    int s = g_cursor[t];
    int e = (bin == NBINS - 1) ? N : g_cursor[t + 1];
    g_hist[t] = 0;                        // restore count invariant for replay
    if (e == s) return;
    int* seg = g_sorted + b * N;

    if (e - s >= 2) {
        for (int a = s + 1; a < e; a++) {
            int key = seg[a];
            int j = a - 1;
            while (j >= s && seg[j] > key) { seg[j + 1] = seg[j]; j--; }
            seg[j + 1] = key;
        }
    }

    int cx = bin / (V * V);
    int cy = (bin / V) % V;
    int cz = bin % V;
    float h = (float)(cx * 10000 + cy * 100 + cz);
    for (int j = s; j < e; j++) {
        out[O_IDX  + b * N + j] = (float)seg[j];
        out[O_HASH + b * N + j] = h;
    }
}

// ---------------------------------------------------------------------------
// neighbour table: PERSISTENT grid-stride kernel, only 2 blocks/SM so chain
// kernels co-reside and truly overlap. One q = one float4 -> 8 batch copies.
__global__ void __launch_bounds__(NBR_THREADS, 2) neighbour_kernel(
    float* __restrict__ out) {
    __shared__ int   s_sel[81];
    __shared__ float s_add[81];
    if (threadIdx.x < 81) {
        int j = threadIdx.x;
        int c = j % 3, m = j / 3;
        int d = (c == 0) ? (m / 9 - 1) : (c == 1) ? ((m / 3) % 3 - 1) : (m % 3 - 1);
        s_sel[j] = c;
        s_add[j] = (float)d;
    }
    __syncthreads();

    const int stride = NBR_BLOCKS * NBR_THREADS;
    float4* pout = (float4*)(out + O_NBR);

    for (int q = blockIdx.x * NBR_THREADS + threadIdx.x; q < PB_F4; q += stride) {
        int e0  = q * 4;
        int vox = e0 / 81;
        int j0  = e0 - vox * 81;
        int x = vox / (V * V);
        int r = vox - x * (V * V);
        int y = r / V;
        int z = r - y * V;
        int zn = z + 1, yn = y, xn = x;
        if (zn == V) { zn = 0; yn = y + 1; if (yn == V) { yn = 0; xn = x + 1; } }
        float xf = (float)x, yf = (float)y, zf = (float)z;
        float xf1 = (float)xn, yf1 = (float)yn, zf1 = (float)zn;

        float4 v;
        float* vp = &v.x;
        #pragma unroll
        for (int k = 0; k < 4; k++) {
            int jk = j0 + k;
            bool w = jk >= 81;
            int jj = w ? jk - 81 : jk;
            int sel = s_sel[jj];
            float cx = (sel == 0) ? (w ? xf1 : xf)
                     : (sel == 1) ? (w ? yf1 : yf)
                                  : (w ? zf1 : zf);
            vp[k] = cx + s_add[jj];
        }

        #pragma unroll
        for (int b = 0; b < B; b++) __stcs(&pout[q + (size_t)b * PB_F4], v);
    }
}

// ---------------------------------------------------------------------------
extern "C" void kernel_launch(void* const* d_in, const int* in_sizes, int n_in,
                              void* d_out, int out_size) {
    const float* pts = (const float*)d_in[0];
    float* out = (float*)d_out;

    static cudaStream_t s_chain = nullptr, s_nbr = nullptr;
    static cudaEvent_t ev_fork = nullptr, ev_a = nullptr, ev_b = nullptr;
    if (s_chain == nullptr) {
        int lo = 0, hi = 0;
        cudaDeviceGetStreamPriorityRange(&lo, &hi);   // hi = greatest priority
        cudaStreamCreateWithPriority(&s_chain, cudaStreamNonBlocking, hi);
        cudaStreamCreateWithPriority(&s_nbr,   cudaStreamNonBlocking, lo);
        cudaEventCreateWithFlags(&ev_fork, cudaEventDisableTiming);
        cudaEventCreateWithFlags(&ev_a,    cudaEventDisableTiming);
        cudaEventCreateWithFlags(&ev_b,    cudaEventDisableTiming);
    }

    // fork from legacy stream
    cudaEventRecord(ev_fork, 0);
    cudaStreamWaitEvent(s_nbr,   ev_fork, 0);
    cudaStreamWaitEvent(s_chain, ev_fork, 0);

    // LOW priority: persistent nbr writer — 2 blocks/SM, leaves room for chain
    neighbour_kernel<<<NBR_BLOCKS, NBR_THREADS, 0, s_nbr>>>(out);
    cudaEventRecord(ev_b, s_nbr);

    // HIGH priority: sort chain — co-resident with nbr, dispatches immediately
    bin_kernel     <<<(B * N / 4 + 255) / 256, 256, 0, s_chain>>>(pts);
    scanA_kernel   <<<B * NTILES, 256, 0, s_chain>>>();
    scanC_kernel   <<<B * NTILES, 256, 0, s_chain>>>(out);
    scatter_kernel <<<(B * N / 4 + 255) / 256, 256, 0, s_chain>>>();
    finalize_kernel<<<(B * NBINS + 255) / 256, 256, 0, s_chain>>>(out);
    cudaEventRecord(ev_a, s_chain);

    // join to legacy stream
    cudaStreamWaitEvent(0, ev_a, 0);
    cudaStreamWaitEvent(0, ev_b, 0);
}